// round 16
// baseline (speedup 1.0000x reference)
#include <cuda_runtime.h>
#include <cuda_fp16.h>
#include <cstdint>

// ===========================================================================
// BitNetSummaryEncoder — HMMA, register-resident W (fp16), fp16 A, smem z.
// FOLDED second MLP layers (exact) + tanh.approx GLU + 2x-unrolled mt loop.
//   k-layout: [0..24 emb | 25..32 gelu_v | 33..56 gelu_p | 57 bias | 58..63 0]
//   16 warps; warp w owns output cols [16w,16w+16) (h and g).
//   Tile = 512 rows; GEMM+LN in 4 subtiles of 128 rows via zbuf smem.
// ===========================================================================

#define THREADS       512
#define ROWS_PER_CTA  512
#define SUB_ROWS      128
#define ZSTRIDE       260

__device__ float d_q[912];          // quant weights + biases staging
__device__ float d_Wfold[512 * 64]; // folded projection (fp32)

// ---------------- smem layout (bytes) --------------------------------------
#define SM_A    0u
#define SM_WH   0u
#define SM_Z    65536u
#define SM_RED  198656u
#define SM_STAT 216064u
#define SM_PAR  217088u
// float offsets within spar:
#define P_CEMB  0       // 320
#define P_REMB  320     // 320
#define P_VW1   640     // 32
#define P_PW1   672     // 288
#define P_VB1   960     // 8
#define P_PB1   968     // 24
#define P_LNG   992     // 256
#define P_LNB   1248    // 256
#define P_END   1504
#define SMEM_BYTES (SM_PAR + P_END * 4)

// ---------------- PTX helpers -----------------------------------------------
__device__ __forceinline__ uint32_t smem_u32(const void* p) {
    uint32_t a;
    asm("{ .reg .u64 t; cvta.to.shared.u64 t, %1; cvt.u32.u64 %0, t; }"
        : "=r"(a) : "l"(p));
    return a;
}
__device__ __forceinline__ void ldsm_x4(uint32_t* r, uint32_t addr) {
    asm volatile("ldmatrix.sync.aligned.m8n8.x4.shared.b16 {%0,%1,%2,%3}, [%4];"
                 : "=r"(r[0]), "=r"(r[1]), "=r"(r[2]), "=r"(r[3]) : "r"(addr));
}
__device__ __forceinline__ void ldsm_x4t(uint32_t* r, uint32_t addr) {
    asm volatile("ldmatrix.sync.aligned.m8n8.x4.trans.shared.b16 {%0,%1,%2,%3}, [%4];"
                 : "=r"(r[0]), "=r"(r[1]), "=r"(r[2]), "=r"(r[3]) : "r"(addr));
}
__device__ __forceinline__ void mma16816(float* d, const uint32_t* a,
                                         const uint32_t* b) {
    asm volatile(
        "mma.sync.aligned.m16n8k16.row.col.f32.f16.f16.f32 "
        "{%0,%1,%2,%3}, {%4,%5,%6,%7}, {%8,%9}, {%0,%1,%2,%3};"
        : "+f"(d[0]), "+f"(d[1]), "+f"(d[2]), "+f"(d[3])
        : "r"(a[0]), "r"(a[1]), "r"(a[2]), "r"(a[3]), "r"(b[0]), "r"(b[1]));
}
__device__ __forceinline__ float gelu_exact(float x) {
    return 0.5f * x * (1.0f + erff(x * 0.7071067811865476f));
}
__device__ __forceinline__ uint32_t pack2h(float a, float b) {
    __half h0 = __float2half_rn(a);
    __half h1 = __float2half_rn(b);
    return (uint32_t)__half_as_ushort(h0) | ((uint32_t)__half_as_ushort(h1) << 16);
}
// h * sigmoid(g) via single-MUFU tanh.approx
__device__ __forceinline__ float fast_glu(float h, float g) {
    float t;
    asm("tanh.approx.f32 %0, %1;" : "=f"(t) : "f"(g * 0.5f));
    float hh = 0.5f * h;
    return fmaf(hh, t, hh);
}

// ---------------------------------------------------------------------------
__global__ void quant_prep_kernel(const float* __restrict__ vw1,
                                  const float* __restrict__ vw2,
                                  const float* __restrict__ pw1,
                                  const float* __restrict__ pw2,
                                  const float* __restrict__ vb1,
                                  const float* __restrict__ vb2,
                                  const float* __restrict__ pb1,
                                  const float* __restrict__ pb2) {
    __shared__ float red[512];
    const float* W; int n; float* out;
    switch (blockIdx.x) {
        case 0:  W = vw1; n = 32;  out = d_q;       break;
        case 1:  W = vw2; n = 48;  out = d_q + 32;  break;
        case 2:  W = pw1; n = 288; out = d_q + 80;  break;
        default: W = pw2; n = 480; out = d_q + 368; break;
    }
    int t = threadIdx.x;
    red[t] = (t < n) ? fabsf(W[t]) : 0.0f;
    __syncthreads();
#pragma unroll
    for (int s = 256; s > 0; s >>= 1) {
        if (t < s) red[t] += red[t + s];
        __syncthreads();
    }
    float scale = red[0] / (float)n;
    if (t < n) {
        float q = rintf(W[t] / (scale + 1e-5f));
        q = fminf(fmaxf(q, -1.0f), 1.0f);
        out[t] = q * scale;
    }
    if (blockIdx.x == 0 && t < 8)  d_q[848 + t] = vb1[t];
    if (blockIdx.x == 1 && t < 6)  d_q[856 + t] = vb2[t];
    if (blockIdx.x == 2 && t < 24) d_q[864 + t] = pb1[t];
    if (blockIdx.x == 3 && t < 20) d_q[888 + t] = pb2[t];
}

// ---------------------------------------------------------------------------
// Fold Vq2/Pq2 (and biases) into the projection (exact linear algebra).
__global__ void fold_kernel(const float* __restrict__ f_wh,
                            const float* __restrict__ f_bh,
                            const float* __restrict__ f_wg,
                            const float* __restrict__ f_bg) {
    const int n = blockIdx.x * blockDim.x + threadIdx.x;
    if (n >= 512) return;
    const float* fw = (n < 256) ? (f_wh + n * 51) : (f_wg + (size_t)(n - 256) * 51);
    const float   fb = (n < 256) ? f_bh[n] : f_bg[n - 256];
    float* Wr = d_Wfold + (size_t)n * 64;
#pragma unroll
    for (int k = 0; k < 25; k++) Wr[k] = fw[k];
#pragma unroll
    for (int j = 0; j < 8; j++) {
        float s = 0.0f;
#pragma unroll
        for (int i = 0; i < 6; i++) s = fmaf(fw[25 + i], d_q[32 + i * 8 + j], s);
        Wr[25 + j] = s;
    }
#pragma unroll
    for (int j = 0; j < 24; j++) {
        float s = 0.0f;
#pragma unroll
        for (int i = 0; i < 20; i++) s = fmaf(fw[31 + i], d_q[368 + i * 24 + j], s);
        Wr[33 + j] = s;
    }
    float b = fb;
#pragma unroll
    for (int i = 0; i < 6; i++)  b = fmaf(fw[25 + i], d_q[856 + i], b);
#pragma unroll
    for (int i = 0; i < 20; i++) b = fmaf(fw[31 + i], d_q[888 + i], b);
    Wr[57] = b;
#pragma unroll
    for (int k = 58; k < 64; k++) Wr[k] = 0.0f;
}

// ---------------------------------------------------------------------------
__global__ void __launch_bounds__(THREADS, 1)
encoder_hmma_kernel(const int* __restrict__ read_count,
                    const int* __restrict__ write_count,
                    const int* __restrict__ fault_count,
                    const int* __restrict__ cow_count,
                    const int* __restrict__ recency,
                    const float* __restrict__ volatility,
                    const float* __restrict__ pressure,
                    const float* __restrict__ count_emb,
                    const float* __restrict__ recency_emb,
                    const float* __restrict__ ln_g,
                    const float* __restrict__ ln_b,
                    float* __restrict__ out,
                    int num_tiles) {
    extern __shared__ char smraw[];
    float* spar = (float*)(smraw + SM_PAR);
    const uint32_t sbase = smem_u32(smraw);
    const int tid = threadIdx.x;
    const int w   = tid >> 5;          // 0..15
    const int lid = tid & 31;

    // ---- build W fp16 in smem from folded fp32 (SW swizzled) ---------------
    for (int i = tid; i < 512 * 64; i += THREADS) {
        int n = i >> 6, k = i & 63;
        uint32_t off = (uint32_t)k * 1024u + ((((uint32_t)n >> 3) ^ ((uint32_t)k & 7)) << 4)
                       + (((uint32_t)n & 7) << 1);
        *(__half*)(smraw + SM_WH + off) = __float2half_rn(d_Wfold[i]);
    }
    for (int i = tid; i < 320; i += THREADS) {
        spar[P_CEMB + i] = count_emb[i];
        spar[P_REMB + i] = recency_emb[i];
    }
    for (int i = tid; i < 32; i += THREADS)  spar[P_VW1 + i] = d_q[i];
    for (int i = tid; i < 288; i += THREADS) spar[P_PW1 + i] = d_q[80 + i];
    if (tid < 8)  spar[P_VB1 + tid] = d_q[848 + tid];
    if (tid < 24) spar[P_PB1 + tid] = d_q[864 + tid];
    if (tid < 256) { spar[P_LNG + tid] = ln_g[tid]; spar[P_LNB + tid] = ln_b[tid]; }
    __syncthreads();

    float*  zbuf  = (float*)(smraw + SM_Z);
    float2* red2  = (float2*)(smraw + SM_RED);
    float2* stat2 = (float2*)(smraw + SM_STAT);
    const float* s_vw1 = spar + P_VW1;
    const float* s_pw1 = spar + P_PW1;
    const float* s_vb1 = spar + P_VB1;
    const float* s_pb1 = spar + P_PB1;

    const int grp = lid >> 3, li = lid & 7;
    const int r0  = lid >> 2;
    const int cql = (lid & 3) << 1;

    // ---- register-resident W fragments (once) -------------------------------
    uint32_t Bf[4][8];
#pragma unroll
    for (int c = 0; c < 2; c++) {
        const int chh = w * 2 + c;
        const int chg = 32 + w * 2 + c;
#pragma unroll
        for (int kh = 0; kh < 2; kh++) {
            int krow = kh * 32 + grp * 8 + li;
            uint32_t rowoff = (uint32_t)krow * 1024u;
            uint32_t swh = (((uint32_t)(chh ^ (krow & 7))) << 4);
            uint32_t swg = (((uint32_t)(chg ^ (krow & 7))) << 4);
            ldsm_x4t(&Bf[c][kh * 4],     sbase + SM_WH + rowoff + swh);
            ldsm_x4t(&Bf[2 + c][kh * 4], sbase + SM_WH + rowoff + swg);
        }
    }
    __syncthreads();   // W frags in regs; smem now A + zbuf

    // -------------------- persistent tile loop ------------------------------
    for (int t = blockIdx.x; t < num_tiles; t += gridDim.x) {
        const size_t rowbase = (size_t)t * ROWS_PER_CTA;

        // ---- phase 0: embeds + FIRST MLP layers only -> A smem --------------
        {
            const size_t myrow = rowbase + (size_t)tid;
            const uint32_t abase = (uint32_t)tid * 128u;
            float v8[8];
            auto store_chunk = [&](int j, const float* v) {
                uint32_t hw[4];
#pragma unroll
                for (int q = 0; q < 4; q++) hw[q] = pack2h(v[2 * q], v[2 * q + 1]);
                uint32_t off = abase + (((uint32_t)(j ^ (tid & 7))) << 4);
                *(uint4*)(smraw + SM_A + off) = make_uint4(hw[0], hw[1], hw[2], hw[3]);
            };
            const int rc = read_count[myrow], wc = write_count[myrow];
            const int fc = fault_count[myrow], cc = cow_count[myrow];
            const int rr = recency[myrow];
#pragma unroll
            for (int d = 0; d < 5; d++) v8[d] = spar[P_CEMB + rc * 5 + d];
#pragma unroll
            for (int d = 0; d < 3; d++) v8[5 + d] = spar[P_CEMB + wc * 5 + d];
            store_chunk(0, v8);
            v8[0] = spar[P_CEMB + wc * 5 + 3];
            v8[1] = spar[P_CEMB + wc * 5 + 4];
#pragma unroll
            for (int d = 0; d < 5; d++) v8[2 + d] = spar[P_CEMB + fc * 5 + d];
            v8[7] = spar[P_CEMB + cc * 5 + 0];
            store_chunk(1, v8);
#pragma unroll
            for (int d = 0; d < 4; d++) v8[d] = spar[P_CEMB + cc * 5 + 1 + d];
#pragma unroll
            for (int d = 0; d < 4; d++) v8[4 + d] = spar[P_REMB + rr * 5 + d];
            store_chunk(2, v8);

            float4 v4 = ((const float4*)volatility)[myrow];
            float va[4] = {v4.x, v4.y, v4.z, v4.w};
            float gv[8];
#pragma unroll
            for (int j = 0; j < 8; j++) {
                float a = s_vb1[j];
#pragma unroll
                for (int i = 0; i < 4; i++) a = fmaf(s_vw1[j * 4 + i], va[i], a);
                gv[j] = gelu_exact(a);
            }
            float4 pA = ((const float4*)pressure)[myrow * 3 + 0];
            float4 pB = ((const float4*)pressure)[myrow * 3 + 1];
            float4 pC = ((const float4*)pressure)[myrow * 3 + 2];
            float pr[12] = {pA.x, pA.y, pA.z, pA.w, pB.x, pB.y, pB.z, pB.w,
                            pC.x, pC.y, pC.z, pC.w};
            float gp[24];
#pragma unroll
            for (int j = 0; j < 24; j++) {
                float a = s_pb1[j];
#pragma unroll
                for (int i = 0; i < 12; i++) a = fmaf(s_pw1[j * 12 + i], pr[i], a);
                gp[j] = gelu_exact(a);
            }
            v8[0] = spar[P_REMB + rr * 5 + 4];
#pragma unroll
            for (int d = 0; d < 7; d++) v8[1 + d] = gv[d];
            store_chunk(3, v8);
            v8[0] = gv[7];
#pragma unroll
            for (int d = 0; d < 7; d++) v8[1 + d] = gp[d];
            store_chunk(4, v8);
#pragma unroll
            for (int d = 0; d < 8; d++) v8[d] = gp[7 + d];
            store_chunk(5, v8);
#pragma unroll
            for (int d = 0; d < 8; d++) v8[d] = gp[15 + d];
            store_chunk(6, v8);
            v8[0] = gp[23]; v8[1] = 1.0f;
#pragma unroll
            for (int d = 2; d < 8; d++) v8[d] = 0.0f;
            store_chunk(7, v8);
        }
        __syncthreads();   // A ready

        // ---- 4 subtiles of 128 rows: GEMM -> zbuf -> stats -> LN store -----
#pragma unroll 1
        for (int sub = 0; sub < 4; sub++) {
#pragma unroll 2
            for (int mt = 0; mt < 8; mt++) {
                float acc[4][4];
#pragma unroll
                for (int c = 0; c < 4; c++)
#pragma unroll
                    for (int i = 0; i < 4; i++) acc[c][i] = 0.0f;

                const int rloc = sub * SUB_ROWS + mt * 16 + ((grp & 1) << 3) + li;
                const uint32_t roff = (uint32_t)rloc * 128u;
#pragma unroll
                for (int ks = 0; ks < 4; ks++) {
                    uint32_t A[4];
                    const int ch = 2 * ks + (grp >> 1);
                    const uint32_t off = roff + (((uint32_t)(ch ^ (rloc & 7))) << 4);
                    ldsm_x4(A, sbase + SM_A + off);
#pragma unroll
                    for (int c = 0; c < 4; c++)
                        mma16816(acc[c], A, &Bf[c][2 * ks]);
                }
                float s0 = 0.f, q0 = 0.f, s8 = 0.f, q8 = 0.f;
                const int zr = mt * 16 + r0;
#pragma unroll
                for (int c = 0; c < 2; c++) {
                    float z0 = fast_glu(acc[c][0], acc[2 + c][0]);
                    float z1 = fast_glu(acc[c][1], acc[2 + c][1]);
                    float z2 = fast_glu(acc[c][2], acc[2 + c][2]);
                    float z3 = fast_glu(acc[c][3], acc[2 + c][3]);
                    const int col = w * 16 + c * 8 + cql;
                    *(float2*)(zbuf + zr * ZSTRIDE + col)       = make_float2(z0, z1);
                    *(float2*)(zbuf + (zr + 8) * ZSTRIDE + col) = make_float2(z2, z3);
                    s0 += z0 + z1;
                    q0 = fmaf(z0, z0, fmaf(z1, z1, q0));
                    s8 += z2 + z3;
                    q8 = fmaf(z2, z2, fmaf(z3, z3, q8));
                }
                s0 += __shfl_xor_sync(0xffffffffu, s0, 1);
                q0 += __shfl_xor_sync(0xffffffffu, q0, 1);
                s8 += __shfl_xor_sync(0xffffffffu, s8, 1);
                q8 += __shfl_xor_sync(0xffffffffu, q8, 1);
                s0 += __shfl_xor_sync(0xffffffffu, s0, 2);
                q0 += __shfl_xor_sync(0xffffffffu, q0, 2);
                s8 += __shfl_xor_sync(0xffffffffu, s8, 2);
                q8 += __shfl_xor_sync(0xffffffffu, q8, 2);
                if ((lid & 3) == 0) {
                    red2[zr * 17 + w]       = make_float2(s0, q0);
                    red2[(zr + 8) * 17 + w] = make_float2(s8, q8);
                }
            }
            __syncthreads();   // zbuf + red2 ready

            if (tid < SUB_ROWS) {
                float s = 0.f, q = 0.f;
#pragma unroll
                for (int k = 0; k < 16; k++) {
                    float2 p = red2[tid * 17 + k];
                    s += p.x;
                    q += p.y;
                }
                float mu = s * (1.0f / 256.0f);
                float var = fmaxf(q * (1.0f / 256.0f) - mu * mu, 0.0f);
                stat2[tid] = make_float2(mu, rsqrtf(var + 1e-5f));
            }
            __syncthreads();   // stats ready

            {
                const float4* lng4 = (const float4*)(spar + P_LNG);
                const float4* lnb4 = (const float4*)(spar + P_LNB);
                float4* out4 = (float4*)(out + (rowbase + (size_t)sub * SUB_ROWS) * 256);
#pragma unroll 4
                for (int i = tid; i < SUB_ROWS * 64; i += THREADS) {
                    const int r = i >> 6, c4 = i & 63;
                    float4 z = *(const float4*)(zbuf + r * ZSTRIDE + c4 * 4);
                    float2 st = stat2[r];
                    float4 gg = lng4[c4];
                    float4 bb = lnb4[c4];
                    z.x = fmaf((z.x - st.x) * st.y, gg.x, bb.x);
                    z.y = fmaf((z.y - st.x) * st.y, gg.y, bb.y);
                    z.z = fmaf((z.z - st.x) * st.y, gg.z, bb.z);
                    z.w = fmaf((z.w - st.x) * st.y, gg.w, bb.w);
                    out4[(size_t)r * 64 + c4] = z;
                }
            }
            __syncthreads();   // zbuf reusable
        }
    }
}

// ---------------------------------------------------------------------------
extern "C" void kernel_launch(void* const* d_in, const int* in_sizes, int n_in,
                              void* d_out, int out_size) {
    const int* read_count  = (const int*)d_in[0];
    const int* write_count = (const int*)d_in[1];
    const int* fault_count = (const int*)d_in[2];
    const int* cow_count   = (const int*)d_in[3];
    const int* recency     = (const int*)d_in[4];
    const float* volatility  = (const float*)d_in[5];
    const float* pressure    = (const float*)d_in[6];
    const float* count_emb   = (const float*)d_in[7];
    const float* recency_emb = (const float*)d_in[8];
    const float* p_w1 = (const float*)d_in[9];
    const float* p_b1 = (const float*)d_in[10];
    const float* p_w2 = (const float*)d_in[11];
    const float* p_b2 = (const float*)d_in[12];
    const float* v_w1 = (const float*)d_in[13];
    const float* v_b1 = (const float*)d_in[14];
    const float* v_w2 = (const float*)d_in[15];
    const float* v_b2 = (const float*)d_in[16];
    const float* f_wh = (const float*)d_in[17];
    const float* f_bh = (const float*)d_in[18];
    const float* f_wg = (const float*)d_in[19];
    const float* f_bg = (const float*)d_in[20];
    const float* ln_g = (const float*)d_in[21];
    const float* ln_b = (const float*)d_in[22];
    float* out = (float*)d_out;

    const int B = in_sizes[0];
    const int num_tiles = B / ROWS_PER_CTA;  // 1024

    int dev = 0, sms = 148;
    cudaGetDevice(&dev);
    cudaDeviceGetAttribute(&sms, cudaDevAttrMultiProcessorCount, dev);
    int grid = num_tiles < sms ? num_tiles : sms;

    quant_prep_kernel<<<4, 512>>>(v_w1, v_w2, p_w1, p_w2,
                                  v_b1, v_b2, p_b1, p_b2);
    fold_kernel<<<1, 512>>>(f_wh, f_bh, f_wg, f_bg);

    cudaFuncSetAttribute(encoder_hmma_kernel,
                         cudaFuncAttributeMaxDynamicSharedMemorySize, SMEM_BYTES);
    encoder_hmma_kernel<<<grid, THREADS, SMEM_BYTES>>>(
        read_count, write_count, fault_count, cow_count, recency,
        volatility, pressure, count_emb, recency_emb,
        ln_g, ln_b, out, num_tiles);
}